// round 11
// baseline (speedup 1.0000x reference)
#include <cuda_runtime.h>
#include <cuda_bf16.h>
#include <math.h>
#include <cstdint>

#define BATCH 2
#define CCH   256
#define HSZ   48
#define NPIX  (HSZ*HSZ)     // 2304
#define NHEAD 8
#define HDIM  32
#define HID   512
#define QT    128
#define KT    128
#define NKT   (NPIX/KT)     // 18
#define RSQ   48            // fp8 q/k smem row stride (32B data + 16 pad)
#define RSV   80            // bf16 v smem row stride (64B data + 16 pad)
#define ONESB 0x3F803F80u   // bf16x2 (1.0, 1.0)

// ---- device scratch ----
__device__ float g_v [BATCH*CCH*NPIX];
__device__ float g_pe[BATCH*CCH*NPIX];
__device__ float g_o [BATCH*CCH*NPIX];
__device__ float g_x1[BATCH*CCH*NPIX];
__device__ float g_h [BATCH*HID*NPIX];
__device__ uint8_t g_q8[BATCH*NHEAD*NPIX*HDIM];        // e4m3 [b,h][n][d], q pre-scaled
__device__ uint8_t g_k8[BATCH*NHEAD*NPIX*HDIM];        // e4m3 [b,h][n][d]
__device__ __nv_bfloat16 g_vb[BATCH*NHEAD*NPIX*HDIM];  // bf16 [b,h][n][d]

__device__ __forceinline__ uint32_t smem_u32(const void* p) {
    uint32_t a;
    asm("{ .reg .u64 t; cvta.to.shared.u64 t, %1; cvt.u32.u64 %0, t; }" : "=r"(a) : "l"(p));
    return a;
}
#define CP_ASYNC16(dst, src) \
    asm volatile("cp.async.ca.shared.global [%0], [%1], 16;" :: "r"(dst), "l"(src))
#define CP_COMMIT() asm volatile("cp.async.commit_group;" ::: "memory")
#define CP_WAIT0()  asm volatile("cp.async.wait_group 0;" ::: "memory")

__device__ __forceinline__ void ldsm_x4(uint32_t addr, uint32_t &r0, uint32_t &r1, uint32_t &r2, uint32_t &r3) {
    asm volatile("ldmatrix.sync.aligned.m8n8.x4.shared.b16 {%0,%1,%2,%3}, [%4];"
        : "=r"(r0),"=r"(r1),"=r"(r2),"=r"(r3) : "r"(addr));
}
__device__ __forceinline__ void ldsm_x4_t(uint32_t addr, uint32_t &r0, uint32_t &r1, uint32_t &r2, uint32_t &r3) {
    asm volatile("ldmatrix.sync.aligned.m8n8.x4.trans.shared.b16 {%0,%1,%2,%3}, [%4];"
        : "=r"(r0),"=r"(r1),"=r"(r2),"=r"(r3) : "r"(addr));
}
__device__ __forceinline__ void mma_bf16(float* c,
    uint32_t a0,uint32_t a1,uint32_t a2,uint32_t a3,uint32_t b0,uint32_t b1) {
    asm volatile("mma.sync.aligned.m16n8k16.row.col.f32.bf16.bf16.f32 "
        "{%0,%1,%2,%3}, {%4,%5,%6,%7}, {%8,%9}, {%0,%1,%2,%3};"
        : "+f"(c[0]),"+f"(c[1]),"+f"(c[2]),"+f"(c[3])
        : "r"(a0),"r"(a1),"r"(a2),"r"(a3),"r"(b0),"r"(b1));
}
__device__ __forceinline__ void mma_fp8(float* c,
    uint32_t a0,uint32_t a1,uint32_t a2,uint32_t a3,uint32_t b0,uint32_t b1) {
    asm volatile("mma.sync.aligned.m16n8k32.row.col.f32.e4m3.e4m3.f32 "
        "{%0,%1,%2,%3}, {%4,%5,%6,%7}, {%8,%9}, {%0,%1,%2,%3};"
        : "+f"(c[0]),"+f"(c[1]),"+f"(c[2]),"+f"(c[3])
        : "r"(a0),"r"(a1),"r"(a2),"r"(a3),"r"(b0),"r"(b1));
}
__device__ __forceinline__ void mma_tf32(float* c,
    uint32_t a0,uint32_t a1,uint32_t a2,uint32_t a3,uint32_t b0,uint32_t b1) {
    asm volatile("mma.sync.aligned.m16n8k8.row.col.f32.tf32.tf32.f32 "
        "{%0,%1,%2,%3}, {%4,%5,%6,%7}, {%8,%9}, {%0,%1,%2,%3};"
        : "+f"(c[0]),"+f"(c[1]),"+f"(c[2]),"+f"(c[3])
        : "r"(a0),"r"(a1),"r"(a2),"r"(a3),"r"(b0),"r"(b1));
}
__device__ __forceinline__ uint32_t pack_bf16x2(float lo, float hi) {
    uint32_t r; asm("cvt.rn.bf16x2.f32 %0, %1, %2;" : "=r"(r) : "f"(hi), "f"(lo)); return r;
}
__device__ __forceinline__ uint32_t ex2_bf16x2(uint32_t x) {
    uint32_t r; asm("ex2.approx.ftz.bf16x2 %0, %1;" : "=r"(r) : "r"(x)); return r;
}
__device__ __forceinline__ uint32_t pack_e4m3_4(float f0, float f1, float f2, float f3) {
    unsigned short lo, hi;
    asm("cvt.rn.satfinite.e4m3x2.f32 %0, %1, %2;" : "=h"(lo) : "f"(f1), "f"(f0));
    asm("cvt.rn.satfinite.e4m3x2.f32 %0, %1, %2;" : "=h"(hi) : "f"(f3), "f"(f2));
    return (uint32_t)lo | ((uint32_t)hi << 16);
}

// ============================================================================
// tf32 GEMM for 1x1 convs. 32o x 64n tile, 64 threads (2 warps, each 32x32 —
// same per-warp MMA density as the proven R6 config, but 2x the CTA count
// for latency hiding across independent CTAs). 2-stage cp.async.
// EPI: 0 none, 1 silu, 2 residual. MODE: 0 fp32 out, 1 fused qkv.
// Buf (floats): As[32][36]=1152 | Bs[32][68]=2176 -> 3328 floats (13312 B) x2.
// ============================================================================
template<int KDIM, int EPI, int MODE>
__global__ void __launch_bounds__(64) gemm_tf32_kernel(
    const float* __restrict__ in, const float* __restrict__ w,
    const float* __restrict__ bias, const float* __restrict__ w2,
    const float* __restrict__ bias2, const float* __restrict__ res,
    float* __restrict__ out, int Odim,
    uint8_t* __restrict__ bq, uint8_t* __restrict__ bk)
{
    __shared__ float smem[2*3328];
    float* stage = smem;                     // [32][68] epilogue overlay

    const int b  = blockIdx.z;
    const int by = blockIdx.y;
    const int n0 = blockIdx.x * 64;
    const int t  = threadIdx.x;
    const int lane = t & 31, wx = t >> 5;    // 2 warps side-by-side in n

    const float* W = w;  const float* Bias = bias;
    int o0 = by * 32;
    bool vpath = false;
    if (MODE == 1 && by >= 16) { W = w2; Bias = bias2; o0 = (by - 16) * 32; vpath = true; }

    float c[2][4][4];
    #pragma unroll
    for (int mi=0;mi<2;mi++) for (int nj=0;nj<4;nj++) for (int q=0;q<4;q++) c[mi][nj][q]=0.f;

    const uint32_t smBase = smem_u32(smem);

    auto copy_tile = [&](int k0, int bb) {
        uint32_t Ab = smBase + bb*13312;
        uint32_t Bb = Ab + 4608;
        #pragma unroll
        for (int i = 0; i < 4; i++) {
            int ci = t + i*64;                       // 0..255 : A 32 rows x 8 chunks
            int o = ci >> 3, kq = ci & 7;
            CP_ASYNC16(Ab + (uint32_t)(o*144 + kq*16),
                       &W[(size_t)(o0 + o)*KDIM + k0 + kq*4]);
        }
        #pragma unroll
        for (int i = 0; i < 8; i++) {
            int ci = t + i*64;                       // 0..511 : B 32 rows x 16 chunks
            int kr = ci >> 4, nc = ci & 15;
            CP_ASYNC16(Bb + (uint32_t)(kr*272 + nc*16),
                       &in[((size_t)b*KDIM + k0 + kr)*NPIX + n0 + nc*4]);
        }
        CP_COMMIT();
    };

    copy_tile(0, 0);
    CP_WAIT0();
    __syncthreads();

    const int KB = KDIM / 32;
    int buf = 0;
    for (int kb = 0; kb < KB; kb++) {
        if (kb + 1 < KB) copy_tile((kb+1)*32, buf ^ 1);
        const uint32_t Ab = smBase + buf*13312;
        const float* Bp = smem + buf*3328 + 1152;
        #pragma unroll
        for (int ks = 0; ks < 4; ks++) {
            uint32_t a[2][4];
            #pragma unroll
            for (int mi = 0; mi < 2; mi++) {
                int row = mi*16 + (lane & 15);
                uint32_t addr = Ab + (uint32_t)row*144 + (uint32_t)(ks*32 + (lane>>4)*16);
                ldsm_x4(addr, a[mi][0], a[mi][1], a[mi][2], a[mi][3]);
            }
            #pragma unroll
            for (int nj = 0; nj < 4; nj++) {
                int col = wx*32 + nj*8 + (lane >> 2);
                int krow = ks*8 + (lane & 3);
                uint32_t b0 = __float_as_uint(Bp[krow*68 + col]);
                uint32_t b1 = __float_as_uint(Bp[(krow+4)*68 + col]);
                mma_tf32(c[0][nj], a[0][0],a[0][1],a[0][2],a[0][3], b0,b1);
                mma_tf32(c[1][nj], a[1][0],a[1][1],a[1][2],a[1][3], b0,b1);
            }
        }
        if (kb + 1 < KB) CP_WAIT0();
        __syncthreads();
        buf ^= 1;
    }

    // ---- stage accums (+bias) into smem [32][68] ----
    #pragma unroll
    for (int mi = 0; mi < 2; mi++) {
        int ol = mi*16 + (lane >> 2);
        float bv0 = Bias[o0 + ol];
        float bv1 = Bias[o0 + ol + 8];
        #pragma unroll
        for (int nj = 0; nj < 4; nj++) {
            int nl = wx*32 + nj*8 + (lane & 3)*2;
            *(float2*)&stage[ol*68 + nl]     = make_float2(c[mi][nj][0]+bv0, c[mi][nj][1]+bv0);
            *(float2*)&stage[(ol+8)*68 + nl] = make_float2(c[mi][nj][2]+bv1, c[mi][nj][3]+bv1);
        }
    }
    __syncthreads();

    if (MODE == 0) {
        #pragma unroll
        for (int i = 0; i < 8; i++) {
            int idx = t + i*64;                  // 512 float4 = 32 x 16
            int o = idx >> 4, nq = (idx & 15) * 4;
            float4 v4 = *(float4*)&stage[o*68 + nq];
            size_t g = ((size_t)b*Odim + o0 + o)*NPIX + n0 + nq;
            if (EPI == 1) {
                v4.x = v4.x/(1.f+__expf(-v4.x)); v4.y = v4.y/(1.f+__expf(-v4.y));
                v4.z = v4.z/(1.f+__expf(-v4.z)); v4.w = v4.w/(1.f+__expf(-v4.w));
            } else if (EPI == 2) {
                float4 r4 = *(const float4*)&res[g];
                v4.x += r4.x; v4.y += r4.y; v4.z += r4.z; v4.w += r4.w;
            }
            *(float4*)&out[g] = v4;
        }
    } else {
        if (!vpath) {
            // by<16: one 32-channel block = q half (by even) or k half (by odd)
            // of head by>>1; d = row. Emit e4m3.
            const float SCQ = (float)(0.17677669529663687 * 1.4426950408889634);
            const bool isq = ((by & 1) == 0);
            const float sc = isq ? SCQ : 1.f;
            uint8_t* dst = isq ? bq : bk;
            size_t bh = (size_t)b*NHEAD + (by >> 1);
            #pragma unroll
            for (int i = 0; i < 4; i++) {
                int idx = t + i*64;              // 256 = 64 n x 4 d-chunks
                int n = idx >> 2, dq = (idx & 3) * 8;
                float f[8];
                #pragma unroll
                for (int j = 0; j < 8; j++)
                    f[j] = stage[(dq + j)*68 + n] * sc;
                uint32_t lo = pack_e4m3_4(f[0],f[1],f[2],f[3]);
                uint32_t hi = pack_e4m3_4(f[4],f[5],f[6],f[7]);
                *(uint2*)&dst[((bh*NPIX + n0 + n))*HDIM + dq] = make_uint2(lo, hi);
            }
        } else {
            // v path: block = head (by-16), d = row. fp32 g_v + bf16 g_vb.
            #pragma unroll
            for (int i = 0; i < 8; i++) {
                int idx = t + i*64;
                int o = idx >> 4, nq = (idx & 15) * 4;
                float4 v4 = *(float4*)&stage[o*68 + nq];
                *(float4*)&out[((size_t)b*CCH + o0 + o)*NPIX + n0 + nq] = v4;
            }
            size_t bh = (size_t)b*NHEAD + (by - 16);
            #pragma unroll
            for (int i = 0; i < 4; i++) {
                int idx = t + i*64;              // 256 = 64 n x 4 d-chunks
                int n = idx >> 2, dq = (idx & 3) * 8;
                __nv_bfloat16 p8[8];
                #pragma unroll
                for (int j = 0; j < 8; j++)
                    p8[j] = __float2bfloat16(stage[(dq + j)*68 + n]);
                *(uint4*)&g_vb[(bh*NPIX + n0 + n)*HDIM + dq] = *(uint4*)p8;
            }
        }
    }
}

// ============================================================================
// Depthwise 7x7 conv
// ============================================================================
__global__ void __launch_bounds__(256) dwconv_kernel(
    const float* __restrict__ vin, const float* __restrict__ pw,
    const float* __restrict__ pb, float* __restrict__ out)
{
    __shared__ float plane[54*54];
    __shared__ float wc[49];
    const int c = blockIdx.x, b = blockIdx.y;
    const int t = threadIdx.x;
    const float* src = &vin[((size_t)b*CCH + c)*NPIX];

    if (t < 49) wc[t] = pw[c*49 + t];
    for (int idx = t; idx < 54*54; idx += 256) {
        int gy = idx / 54 - 3, gx = idx % 54 - 3;
        plane[idx] = (gy >= 0 && gy < HSZ && gx >= 0 && gx < HSZ) ? src[gy*HSZ + gx] : 0.f;
    }
    __syncthreads();
    float bias = pb[c];
    for (int p = t; p < NPIX; p += 256) {
        int y = p / HSZ, x = p % HSZ;
        float acc = bias;
        #pragma unroll
        for (int dy = 0; dy < 7; dy++)
            #pragma unroll
            for (int dx = 0; dx < 7; dx++)
                acc += plane[(y+dy)*54 + (x+dx)] * wc[dy*7 + dx];
        out[((size_t)b*CCH + c)*NPIX + p] = acc;
    }
}

// ============================================================================
// Flash attention: fp8 e4m3 Q*K^T (m16n8k32) + bf16 P*V. Split-K over warps:
// 8 warps = 4 query-groups x 2 key-halves. Q pre-scaled by scale*log2e;
// softmax = cvt+ex2 bf16x2; row sums via ones-MMA.
// ============================================================================
__global__ void __launch_bounds__(256, 2) attn_mma_kernel(
    const uint8_t* __restrict__ qT8, const uint8_t* __restrict__ kT8,
    const __nv_bfloat16* __restrict__ vT, const float* __restrict__ pe,
    float* __restrict__ o_out)
{
    __shared__ __align__(16) unsigned char sm[38912];
    const int b  = blockIdx.z, h = blockIdx.y;
    const int n0 = blockIdx.x * QT;
    const int t  = threadIdx.x;
    const int lane = t & 31, w = t >> 5;
    const int qg = w >> 1, kh = w & 1;
    const size_t bh = (size_t)b*NHEAD + h;
    const uint32_t smQ = smem_u32(sm);

    const uint8_t* kg0 = kT8 + bh*NPIX*HDIM;
    const __nv_bfloat16* vg0 = vT + (bh*NPIX)*HDIM;

    auto copy_kv = [&](int m0, int bb) {
        uint32_t kb = smQ + 6144 + bb*16384;
        uint32_t vbp = kb + 6144;
        const uint8_t* kg = kg0 + (size_t)m0*HDIM;
        const __nv_bfloat16* vg = vg0 + (size_t)m0*HDIM;
        CP_ASYNC16(kb + (t>>1)*RSQ + (t&1)*16,        kg + t*16);
        CP_ASYNC16(vbp + (t>>2)*RSV + (t&3)*16,       vg + (t>>2)*HDIM + (t&3)*8);
        CP_ASYNC16(vbp + ((t>>2)+64)*RSV + (t&3)*16,  vg + ((t>>2)+64)*HDIM + (t&3)*8);
        CP_COMMIT();
    };

    {
        const uint8_t* qg8 = qT8 + (bh*NPIX + (size_t)n0)*HDIM;
        CP_ASYNC16(smQ + (t>>1)*RSQ + (t&1)*16, qg8 + t*16);
        CP_COMMIT();
        copy_kv(0, 0);
        CP_WAIT0();
    }
    __syncthreads();

    uint32_t aq[2][4];
    #pragma unroll
    for (int mf = 0; mf < 2; mf++) {
        int r  = qg*32 + mf*16 + (lane & 7) + ((lane >> 3) & 1)*8;
        int cb = (lane >> 4)*16;
        ldsm_x4(smQ + r*RSQ + cb, aq[mf][0],aq[mf][1],aq[mf][2],aq[mf][3]);
    }

    float osum[2][4][4] = {};
    float ssum[2][4] = {};
    const int krow = (lane & 7) + (lane >> 4)*8;
    const int kcol = ((lane >> 3) & 1)*16;
    const int vrow = (lane & 7) + ((lane >> 3) & 1)*8;
    const int vcol = (lane >> 4)*16;
    const int kb0  = kh*64;

    int buf = 0;
    for (int kt = 0; kt < NKT; kt++) {
        if (kt + 1 < NKT) copy_kv((kt+1)*KT, buf ^ 1);
        const uint32_t smK = smQ + 6144 + buf*16384;
        const uint32_t smV = smK + 6144;

        #pragma unroll
        for (int jp = 0; jp < 4; jp++) {
            uint32_t kbase = smK + (kb0 + jp*16 + krow)*RSQ + kcol;
            uint32_t b0,b1,b2,b3;
            ldsm_x4(kbase, b0,b1,b2,b3);
            uint32_t vbase = smV + (kb0 + jp*16 + vrow)*RSV + vcol;
            uint32_t v0,v1,v2,v3,v4,v5,v6,v7;
            ldsm_x4_t(vbase,      v0,v1,v2,v3);
            ldsm_x4_t(vbase + 32, v4,v5,v6,v7);
            #pragma unroll
            for (int mf = 0; mf < 2; mf++) {
                float c0[4] = {0.f,0.f,0.f,0.f};
                float c1[4] = {0.f,0.f,0.f,0.f};
                mma_fp8(c0, aq[mf][0],aq[mf][1],aq[mf][2],aq[mf][3], b0,b1);
                mma_fp8(c1, aq[mf][0],aq[mf][1],aq[mf][2],aq[mf][3], b2,b3);
                uint32_t a0 = ex2_bf16x2(pack_bf16x2(c0[0], c0[1]));
                uint32_t a1 = ex2_bf16x2(pack_bf16x2(c0[2], c0[3]));
                uint32_t a2 = ex2_bf16x2(pack_bf16x2(c1[0], c1[1]));
                uint32_t a3 = ex2_bf16x2(pack_bf16x2(c1[2], c1[3]));
                mma_bf16(ssum[mf],    a0,a1,a2,a3, ONESB, ONESB);
                mma_bf16(osum[mf][0], a0,a1,a2,a3, v0,v1);
                mma_bf16(osum[mf][1], a0,a1,a2,a3, v2,v3);
                mma_bf16(osum[mf][2], a0,a1,a2,a3, v4,v5);
                mma_bf16(osum[mf][3], a0,a1,a2,a3, v6,v7);
            }
        }
        if (kt + 1 < NKT) CP_WAIT0();
        __syncthreads();
        buf ^= 1;
    }

    float* red = (float*)(sm + 16384);   // 4 qg x 40 vals x 32 lanes = 20 KB
    if (kh == 1) {
        #pragma unroll
        for (int mf = 0; mf < 2; mf++) {
            #pragma unroll
            for (int nj = 0; nj < 4; nj++)
                #pragma unroll
                for (int q = 0; q < 4; q++)
                    red[(qg*40 + mf*16 + nj*4 + q)*32 + lane] = osum[mf][nj][q];
            #pragma unroll
            for (int q = 0; q < 4; q++)
                red[(qg*40 + 32 + mf*4 + q)*32 + lane] = ssum[mf][q];
        }
    }
    __syncthreads();

    float* stage = (float*)sm;           // [32 d][128 q], 16 KB
    if (kh == 0) {
        #pragma unroll
        for (int mf = 0; mf < 2; mf++) {
            #pragma unroll
            for (int nj = 0; nj < 4; nj++)
                #pragma unroll
                for (int q = 0; q < 4; q++)
                    osum[mf][nj][q] += red[(qg*40 + mf*16 + nj*4 + q)*32 + lane];
            ssum[mf][0] += red[(qg*40 + 32 + mf*4 + 0)*32 + lane];
            ssum[mf][2] += red[(qg*40 + 32 + mf*4 + 2)*32 + lane];
        }
        #pragma unroll
        for (int mf = 0; mf < 2; mf++) {
            float inv0 = 1.f / ssum[mf][0], inv1 = 1.f / ssum[mf][2];
            int rl = qg*32 + mf*16 + (lane >> 2), rh = rl + 8;
            int d0 = (lane & 3)*2;
            #pragma unroll
            for (int nj = 0; nj < 4; nj++) {
                stage[(nj*8 + d0    )*128 + rl] = osum[mf][nj][0]*inv0;
                stage[(nj*8 + d0 + 1)*128 + rl] = osum[mf][nj][1]*inv0;
                stage[(nj*8 + d0    )*128 + rh] = osum[mf][nj][2]*inv1;
                stage[(nj*8 + d0 + 1)*128 + rh] = osum[mf][nj][3]*inv1;
            }
        }
    }
    __syncthreads();

    size_t obase = ((size_t)b*CCH + h*HDIM)*NPIX + n0;
    #pragma unroll
    for (int i = 0; i < 16; i++) {
        int idx = t + i*256;
        int d = idx >> 7, q = idx & 127;
        size_t g = obase + (size_t)d*NPIX + q;
        o_out[g] = stage[idx] + pe[g];
    }
}

// ============================================================================
extern "C" void kernel_launch(void* const* d_in, const int* in_sizes, int n_in,
                              void* d_out, int out_size)
{
    const float* x      = (const float*)d_in[0];
    const float* qk_w   = (const float*)d_in[1];
    const float* qk_b   = (const float*)d_in[2];
    const float* v_w    = (const float*)d_in[3];
    const float* v_b    = (const float*)d_in[4];
    const float* pe_w   = (const float*)d_in[5];
    const float* pe_b   = (const float*)d_in[6];
    const float* proj_w = (const float*)d_in[7];
    const float* proj_b = (const float*)d_in[8];
    const float* fc1_w  = (const float*)d_in[9];
    const float* fc1_b  = (const float*)d_in[10];
    const float* fc2_w  = (const float*)d_in[11];
    const float* fc2_b  = (const float*)d_in[12];
    float* out = (float*)d_out;

    float *vb, *peb, *ob, *x1b, *hb;
    uint8_t *q8b, *k8b;
    __nv_bfloat16 *vbb;
    cudaGetSymbolAddress((void**)&vb,  g_v);
    cudaGetSymbolAddress((void**)&peb, g_pe);
    cudaGetSymbolAddress((void**)&ob,  g_o);
    cudaGetSymbolAddress((void**)&x1b, g_x1);
    cudaGetSymbolAddress((void**)&hb,  g_h);
    cudaGetSymbolAddress((void**)&q8b, g_q8);
    cudaGetSymbolAddress((void**)&k8b, g_k8);
    cudaGetSymbolAddress((void**)&vbb, g_vb);

    const int NT = NPIX / 64;   // 36

    // qkv: by 0..15 -> qk (32-ch half-heads), by 16..23 -> v heads
    gemm_tf32_kernel<CCH, 0, 1><<<dim3(NT, 24, BATCH), 64>>>(
        x, qk_w, qk_b, v_w, v_b, nullptr, vb, CCH, q8b, k8b);
    dwconv_kernel<<<dim3(CCH, BATCH), 256>>>(vb, pe_w, pe_b, peb);
    attn_mma_kernel<<<dim3(NPIX/QT, NHEAD, BATCH), 256>>>(q8b, k8b, vbb, peb, ob);
    gemm_tf32_kernel<CCH, 2, 0><<<dim3(NT, 8, BATCH), 64>>>(
        ob, proj_w, proj_b, nullptr, nullptr, x, x1b, CCH, nullptr, nullptr);
    gemm_tf32_kernel<CCH, 1, 0><<<dim3(NT, 16, BATCH), 64>>>(
        x1b, fc1_w, fc1_b, nullptr, nullptr, nullptr, hb, HID, nullptr, nullptr);
    gemm_tf32_kernel<HID, 2, 0><<<dim3(NT, 8, BATCH), 64>>>(
        hb, fc2_w, fc2_b, nullptr, nullptr, x1b, out, CCH, nullptr, nullptr);
}

// round 14
// speedup vs baseline: 1.1713x; 1.1713x over previous
#include <cuda_runtime.h>
#include <cuda_bf16.h>
#include <math.h>
#include <cstdint>

#define BATCH 2
#define CCH   256
#define HSZ   48
#define NPIX  (HSZ*HSZ)     // 2304
#define NHEAD 8
#define HDIM  32
#define HID   512
#define QT    128
#define KT    128
#define NKT   (NPIX/KT)     // 18
#define RSQ   48            // fp8 q/k smem row stride
#define RSV   80            // bf16 v smem row stride
#define RSA   80            // bf16 gemm A row stride (64B data + 16 pad)
#define RSB   144           // bf16 gemm B row stride (128B data + 16 pad)
#define ONESB 0x3F803F80u   // bf16x2 (1.0, 1.0)

// ---- device scratch ----
__device__ float g_v [BATCH*CCH*NPIX];
__device__ float g_pe[BATCH*CCH*NPIX];
__device__ float g_x1[BATCH*CCH*NPIX];
__device__ uint8_t g_q8[BATCH*NHEAD*NPIX*HDIM];        // e4m3 [b,h][n][d], q pre-scaled
__device__ uint8_t g_k8[BATCH*NHEAD*NPIX*HDIM];        // e4m3
__device__ __nv_bfloat16 g_vb [BATCH*NHEAD*NPIX*HDIM]; // bf16 [b,h][n][d]
__device__ __nv_bfloat16 g_ob [BATCH*CCH*NPIX];        // bf16 o+pe [b][c][n]
__device__ __nv_bfloat16 g_x1b[BATCH*CCH*NPIX];        // bf16 x1
__device__ __nv_bfloat16 g_hb [BATCH*HID*NPIX];        // bf16 h

__device__ __forceinline__ uint32_t smem_u32(const void* p) {
    uint32_t a;
    asm("{ .reg .u64 t; cvta.to.shared.u64 t, %1; cvt.u32.u64 %0, t; }" : "=r"(a) : "l"(p));
    return a;
}
#define CP_ASYNC16(dst, src) \
    asm volatile("cp.async.ca.shared.global [%0], [%1], 16;" :: "r"(dst), "l"(src))
#define CP_COMMIT() asm volatile("cp.async.commit_group;" ::: "memory")
#define CP_WAIT0()  asm volatile("cp.async.wait_group 0;" ::: "memory")
#define CP_WAIT1()  asm volatile("cp.async.wait_group 1;" ::: "memory")

__device__ __forceinline__ void ldsm_x4(uint32_t addr, uint32_t &r0, uint32_t &r1, uint32_t &r2, uint32_t &r3) {
    asm volatile("ldmatrix.sync.aligned.m8n8.x4.shared.b16 {%0,%1,%2,%3}, [%4];"
        : "=r"(r0),"=r"(r1),"=r"(r2),"=r"(r3) : "r"(addr));
}
__device__ __forceinline__ void ldsm_x4_t(uint32_t addr, uint32_t &r0, uint32_t &r1, uint32_t &r2, uint32_t &r3) {
    asm volatile("ldmatrix.sync.aligned.m8n8.x4.trans.shared.b16 {%0,%1,%2,%3}, [%4];"
        : "=r"(r0),"=r"(r1),"=r"(r2),"=r"(r3) : "r"(addr));
}
__device__ __forceinline__ void mma_bf16(float* c,
    uint32_t a0,uint32_t a1,uint32_t a2,uint32_t a3,uint32_t b0,uint32_t b1) {
    asm volatile("mma.sync.aligned.m16n8k16.row.col.f32.bf16.bf16.f32 "
        "{%0,%1,%2,%3}, {%4,%5,%6,%7}, {%8,%9}, {%0,%1,%2,%3};"
        : "+f"(c[0]),"+f"(c[1]),"+f"(c[2]),"+f"(c[3])
        : "r"(a0),"r"(a1),"r"(a2),"r"(a3),"r"(b0),"r"(b1));
}
__device__ __forceinline__ void mma_fp8(float* c,
    uint32_t a0,uint32_t a1,uint32_t a2,uint32_t a3,uint32_t b0,uint32_t b1) {
    asm volatile("mma.sync.aligned.m16n8k32.row.col.f32.e4m3.e4m3.f32 "
        "{%0,%1,%2,%3}, {%4,%5,%6,%7}, {%8,%9}, {%0,%1,%2,%3};"
        : "+f"(c[0]),"+f"(c[1]),"+f"(c[2]),"+f"(c[3])
        : "r"(a0),"r"(a1),"r"(a2),"r"(a3),"r"(b0),"r"(b1));
}
__device__ __forceinline__ void mma_tf32(float* c,
    uint32_t a0,uint32_t a1,uint32_t a2,uint32_t a3,uint32_t b0,uint32_t b1) {
    asm volatile("mma.sync.aligned.m16n8k8.row.col.f32.tf32.tf32.f32 "
        "{%0,%1,%2,%3}, {%4,%5,%6,%7}, {%8,%9}, {%0,%1,%2,%3};"
        : "+f"(c[0]),"+f"(c[1]),"+f"(c[2]),"+f"(c[3])
        : "r"(a0),"r"(a1),"r"(a2),"r"(a3),"r"(b0),"r"(b1));
}
__device__ __forceinline__ uint32_t pack_bf16x2(float lo, float hi) {
    uint32_t r; asm("cvt.rn.bf16x2.f32 %0, %1, %2;" : "=r"(r) : "f"(hi), "f"(lo)); return r;
}
__device__ __forceinline__ uint32_t ex2_bf16x2(uint32_t x) {
    uint32_t r; asm("ex2.approx.ftz.bf16x2 %0, %1;" : "=r"(r) : "r"(x)); return r;
}
__device__ __forceinline__ uint32_t pack_e4m3_4(float f0, float f1, float f2, float f3) {
    unsigned short lo, hi;
    asm("cvt.rn.satfinite.e4m3x2.f32 %0, %1, %2;" : "=h"(lo) : "f"(f1), "f"(f0));
    asm("cvt.rn.satfinite.e4m3x2.f32 %0, %1, %2;" : "=h"(hi) : "f"(f3), "f"(f2));
    return (uint32_t)lo | ((uint32_t)hi << 16);
}

// ============================================================================
// tf32 GEMM for the qkv conv (R6/R10 proven config: 64x64, 128 thr, 2-stage).
// by<8: q/k half-heads -> e4m3; by>=8: v head -> fp32 g_v + bf16 g_vb.
// ============================================================================
template<int KDIM>
__global__ void __launch_bounds__(128) gemm_qkv_kernel(
    const float* __restrict__ in, const float* __restrict__ w,
    const float* __restrict__ bias, const float* __restrict__ w2,
    const float* __restrict__ bias2, float* __restrict__ vout,
    uint8_t* __restrict__ bq, uint8_t* __restrict__ bk)
{
    __shared__ float smem[2*4480];
    float* stage = smem;

    const int b  = blockIdx.z;
    const int by = blockIdx.y;
    const int n0 = blockIdx.x * 64;
    const int t  = threadIdx.x;
    const int lane = t & 31, wrp = t >> 5;
    const int wy = wrp >> 1, wx = wrp & 1;

    const float* W = w;  const float* Bias = bias;
    int o0 = by * 64;
    bool vpath = false;
    if (by >= 8) { W = w2; Bias = bias2; o0 = (by - 8) * 64; vpath = true; }

    float c[2][4][4];
    #pragma unroll
    for (int mi=0;mi<2;mi++) for (int nj=0;nj<4;nj++) for (int q=0;q<4;q++) c[mi][nj][q]=0.f;

    const uint32_t smBase = smem_u32(smem);

    auto copy_tile = [&](int k0, int bb) {
        uint32_t Ab = smBase + bb*17920;
        uint32_t Bb = Ab + 9216;
        #pragma unroll
        for (int i = 0; i < 4; i++) {
            int ci = t + i*128;
            int o = ci >> 3, kq = ci & 7;
            CP_ASYNC16(Ab + (uint32_t)(o*144 + kq*16),
                       &W[(size_t)(o0 + o)*KDIM + k0 + kq*4]);
        }
        #pragma unroll
        for (int i = 0; i < 4; i++) {
            int ci = t + i*128;
            int kr = ci >> 4, nc = ci & 15;
            CP_ASYNC16(Bb + (uint32_t)(kr*272 + nc*16),
                       &in[((size_t)b*KDIM + k0 + kr)*NPIX + n0 + nc*4]);
        }
        CP_COMMIT();
    };

    copy_tile(0, 0);
    CP_WAIT0();
    __syncthreads();

    const int KB = KDIM / 32;
    int buf = 0;
    for (int kb = 0; kb < KB; kb++) {
        if (kb + 1 < KB) copy_tile((kb+1)*32, buf ^ 1);
        const uint32_t Ab = smBase + buf*17920;
        const float* Bp = smem + buf*4480 + 2304;
        #pragma unroll
        for (int ks = 0; ks < 4; ks++) {
            uint32_t a[2][4];
            #pragma unroll
            for (int mi = 0; mi < 2; mi++) {
                int row = wy*32 + mi*16 + (lane & 15);
                uint32_t addr = Ab + (uint32_t)row*144 + (uint32_t)(ks*32 + (lane>>4)*16);
                ldsm_x4(addr, a[mi][0], a[mi][1], a[mi][2], a[mi][3]);
            }
            #pragma unroll
            for (int nj = 0; nj < 4; nj++) {
                int col = wx*32 + nj*8 + (lane >> 2);
                int krow = ks*8 + (lane & 3);
                uint32_t b0 = __float_as_uint(Bp[krow*68 + col]);
                uint32_t b1 = __float_as_uint(Bp[(krow+4)*68 + col]);
                mma_tf32(c[0][nj], a[0][0],a[0][1],a[0][2],a[0][3], b0,b1);
                mma_tf32(c[1][nj], a[1][0],a[1][1],a[1][2],a[1][3], b0,b1);
            }
        }
        if (kb + 1 < KB) CP_WAIT0();
        __syncthreads();
        buf ^= 1;
    }

    #pragma unroll
    for (int mi = 0; mi < 2; mi++) {
        int ol = wy*32 + mi*16 + (lane >> 2);
        float bv0 = Bias[o0 + ol];
        float bv1 = Bias[o0 + ol + 8];
        #pragma unroll
        for (int nj = 0; nj < 4; nj++) {
            int nl = wx*32 + nj*8 + (lane & 3)*2;
            *(float2*)&stage[ol*68 + nl]     = make_float2(c[mi][nj][0]+bv0, c[mi][nj][1]+bv0);
            *(float2*)&stage[(ol+8)*68 + nl] = make_float2(c[mi][nj][2]+bv1, c[mi][nj][3]+bv1);
        }
    }
    __syncthreads();

    if (!vpath) {
        const float SCQ = (float)(0.17677669529663687 * 1.4426950408889634);
        size_t bh = (size_t)b*NHEAD + by;
        #pragma unroll
        for (int i = 0; i < 4; i++) {
            int idx = t + i*128;            // < 512
            int isk = idx >> 8;
            int r = idx & 255;
            int n = r >> 2, dq = (r & 3) * 8;
            float sc = isk ? 1.f : SCQ;
            float f[8];
            #pragma unroll
            for (int j = 0; j < 8; j++)
                f[j] = stage[(isk*32 + dq + j)*68 + n] * sc;
            uint32_t lo = pack_e4m3_4(f[0],f[1],f[2],f[3]);
            uint32_t hi = pack_e4m3_4(f[4],f[5],f[6],f[7]);
            uint8_t* dst = isk ? bk : bq;
            *(uint2*)&dst[((bh*NPIX + n0 + n))*HDIM + dq] = make_uint2(lo, hi);
        }
    } else {
        #pragma unroll
        for (int i = 0; i < 8; i++) {
            int idx = t + i*128;
            int o = idx >> 4, nq = (idx & 15) * 4;
            float4 v4 = *(float4*)&stage[o*68 + nq];
            *(float4*)&vout[((size_t)b*CCH + o0 + o)*NPIX + n0 + nq] = v4;
        }
        #pragma unroll
        for (int i = 0; i < 4; i++) {
            int idx = t + i*128;            // < 512
            int n = idx >> 3, row = (idx & 7) * 8;
            int ch = o0 + row;
            size_t bh = (size_t)b*NHEAD + (ch >> 5);
            int d = ch & 31;
            __nv_bfloat16 p8[8];
            #pragma unroll
            for (int j = 0; j < 8; j++)
                p8[j] = __float2bfloat16(stage[(row + j)*68 + n]);
            *(uint4*)&g_vb[(bh*NPIX + n0 + n)*HDIM + d] = *(uint4*)p8;
        }
    }
}

// ============================================================================
// bf16 GEMM for proj/fc1/fc2. 64o x 64n, 128 thr (2x2 warps of 32x32).
// B = bf16 activations via cp.async; A = fp32 weights LDG->cvt->STS bf16.
// 16 m16n8k16 MMA per warp per 32-k block (half the tf32 count).
// EPI: 1 silu, 2 residual. OUTB: 0 fp32 only, 1 fp32+bf16 aux, 2 bf16 only.
// Buf: A[64*RSA]=5120B + B[32*RSB]=4608B = 9728B x2. stage fp32 [64][68] overlay.
// ============================================================================
template<int KDIM, int EPI, int OUTB>
__global__ void __launch_bounds__(128) gemm_bf16_kernel(
    const __nv_bfloat16* __restrict__ in, const float* __restrict__ w,
    const float* __restrict__ bias, const float* __restrict__ res,
    float* __restrict__ out, __nv_bfloat16* __restrict__ aux, int Odim)
{
    __shared__ __align__(16) unsigned char sm[2*9728];
    float* stage = (float*)sm;               // [64][68] fp32, 17408B <= 19456B

    const int b  = blockIdx.z;
    const int o0 = blockIdx.y * 64;
    const int n0 = blockIdx.x * 64;
    const int t  = threadIdx.x;
    const int lane = t & 31, wrp = t >> 5;
    const int wy = wrp >> 1, wx = wrp & 1;

    float c[2][4][4];
    #pragma unroll
    for (int mi=0;mi<2;mi++) for (int nj=0;nj<4;nj++) for (int q=0;q<4;q++) c[mi][nj][q]=0.f;

    const uint32_t smBase = smem_u32(sm);
    const int KB = KDIM / 32;

    float4 ra[4];
    auto ldgA = [&](int k0) {
        #pragma unroll
        for (int i = 0; i < 4; i++) {
            int ci = t + i*128;                  // 0..511
            int o = ci >> 3, kq = ci & 7;
            ra[i] = *(const float4*)&w[(size_t)(o0 + o)*KDIM + k0 + kq*4];
        }
    };
    auto stsA = [&](int bb) {
        #pragma unroll
        for (int i = 0; i < 4; i++) {
            int ci = t + i*128;
            int o = ci >> 3, kq = ci & 7;
            uint32_t lo = pack_bf16x2(ra[i].x, ra[i].y);
            uint32_t hi = pack_bf16x2(ra[i].z, ra[i].w);
            *(uint2*)(sm + bb*9728 + o*RSA + kq*8) = make_uint2(lo, hi);
        }
    };
    auto cpB = [&](int k0, int bb) {
        uint32_t Bb = smBase + bb*9728 + 5120;
        #pragma unroll
        for (int i = 0; i < 2; i++) {
            int ci = t + i*128;                  // 0..255
            int kr = ci >> 3, nc = ci & 7;
            CP_ASYNC16(Bb + (uint32_t)(kr*RSB + nc*16),
                       &in[((size_t)b*KDIM + k0 + kr)*NPIX + n0 + nc*8]);
        }
        CP_COMMIT();
    };

    ldgA(0);
    cpB(0, 0);

    int buf = 0;
    for (int kb = 0; kb < KB; kb++) {
        __syncthreads();                 // compute kb-1 fully done (buffer reuse)
        stsA(buf);
        if (kb + 1 < KB) {
            cpB((kb+1)*32, buf ^ 1);
            ldgA((kb+1)*32);
            CP_WAIT1();                  // B(kb) resident; B(kb+1) in flight
        } else {
            CP_WAIT0();
        }
        __syncthreads();

        const uint32_t Ab = smBase + buf*9728;
        const uint32_t Bb = Ab + 5120;
        #pragma unroll
        for (int kk = 0; kk < 2; kk++) {
            uint32_t a[2][4];
            #pragma unroll
            for (int mi = 0; mi < 2; mi++) {
                int row = wy*32 + mi*16 + (lane & 7) + ((lane >> 3) & 1)*8;
                ldsm_x4(Ab + (uint32_t)(row*RSA + kk*32 + (lane>>4)*16),
                        a[mi][0], a[mi][1], a[mi][2], a[mi][3]);
            }
            int brow = kk*16 + (lane & 7) + ((lane >> 3) & 1)*8;
            uint32_t bbase = Bb + (uint32_t)(brow*RSB + wx*64 + (lane>>4)*16);
            uint32_t v0,v1,v2,v3,v4,v5,v6,v7;
            ldsm_x4_t(bbase,      v0,v1,v2,v3);
            ldsm_x4_t(bbase + 32, v4,v5,v6,v7);
            #pragma unroll
            for (int mi = 0; mi < 2; mi++) {
                mma_bf16(c[mi][0], a[mi][0],a[mi][1],a[mi][2],a[mi][3], v0,v1);
                mma_bf16(c[mi][1], a[mi][0],a[mi][1],a[mi][2],a[mi][3], v2,v3);
                mma_bf16(c[mi][2], a[mi][0],a[mi][1],a[mi][2],a[mi][3], v4,v5);
                mma_bf16(c[mi][3], a[mi][0],a[mi][1],a[mi][2],a[mi][3], v6,v7);
            }
        }
        buf ^= 1;
    }
    __syncthreads();                     // buffers dead; stage overlay safe

    // ---- stage accums (+bias) into smem [64][68] fp32 ----
    #pragma unroll
    for (int mi = 0; mi < 2; mi++) {
        int ol = wy*32 + mi*16 + (lane >> 2);
        float bv0 = bias[o0 + ol];
        float bv1 = bias[o0 + ol + 8];
        #pragma unroll
        for (int nj = 0; nj < 4; nj++) {
            int nl = wx*32 + nj*8 + (lane & 3)*2;
            *(float2*)&stage[ol*68 + nl]     = make_float2(c[mi][nj][0]+bv0, c[mi][nj][1]+bv0);
            *(float2*)&stage[(ol+8)*68 + nl] = make_float2(c[mi][nj][2]+bv1, c[mi][nj][3]+bv1);
        }
    }
    __syncthreads();

    // ---- write: 1024 n-pairs over 64 o rows ----
    #pragma unroll
    for (int i = 0; i < 8; i++) {
        int idx = t + i*128;                 // 0..1023
        int o = idx >> 4, np = (idx & 15) * 4;
        size_t g = ((size_t)b*Odim + o0 + o)*NPIX + n0 + np;
        float v[4];
        v[0] = stage[o*68 + np];     v[1] = stage[o*68 + np + 1];
        v[2] = stage[o*68 + np + 2]; v[3] = stage[o*68 + np + 3];
        if (EPI == 1) {
            #pragma unroll
            for (int j = 0; j < 4; j++) v[j] = v[j] / (1.f + __expf(-v[j]));
        } else if (EPI == 2) {
            float4 r4 = *(const float4*)&res[g];
            v[0] += r4.x; v[1] += r4.y; v[2] += r4.z; v[3] += r4.w;
        }
        if (OUTB != 2)
            *(float4*)&out[g] = make_float4(v[0], v[1], v[2], v[3]);
        if (OUTB != 0) {
            uint32_t lo = pack_bf16x2(v[0], v[1]);
            uint32_t hi = pack_bf16x2(v[2], v[3]);
            *(uint2*)&aux[g] = make_uint2(lo, hi);
        }
    }
}

// ============================================================================
// Depthwise 7x7 conv
// ============================================================================
__global__ void __launch_bounds__(256) dwconv_kernel(
    const float* __restrict__ vin, const float* __restrict__ pw,
    const float* __restrict__ pb, float* __restrict__ out)
{
    __shared__ float plane[54*54];
    __shared__ float wc[49];
    const int c = blockIdx.x, b = blockIdx.y;
    const int t = threadIdx.x;
    const float* src = &vin[((size_t)b*CCH + c)*NPIX];

    if (t < 49) wc[t] = pw[c*49 + t];
    for (int idx = t; idx < 54*54; idx += 256) {
        int gy = idx / 54 - 3, gx = idx % 54 - 3;
        plane[idx] = (gy >= 0 && gy < HSZ && gx >= 0 && gx < HSZ) ? src[gy*HSZ + gx] : 0.f;
    }
    __syncthreads();
    float bias = pb[c];
    for (int p = t; p < NPIX; p += 256) {
        int y = p / HSZ, x = p % HSZ;
        float acc = bias;
        #pragma unroll
        for (int dy = 0; dy < 7; dy++)
            #pragma unroll
            for (int dx = 0; dx < 7; dx++)
                acc += plane[(y+dy)*54 + (x+dx)] * wc[dy*7 + dx];
        out[((size_t)b*CCH + c)*NPIX + p] = acc;
    }
}

// ============================================================================
// Flash attention: fp8 e4m3 Q*K^T + bf16 P*V. Split-K over warps.
// Epilogue: o_norm + pe -> bf16 g_ob.
// ============================================================================
__global__ void __launch_bounds__(256, 2) attn_mma_kernel(
    const uint8_t* __restrict__ qT8, const uint8_t* __restrict__ kT8,
    const __nv_bfloat16* __restrict__ vT, const float* __restrict__ pe,
    __nv_bfloat16* __restrict__ o_out)
{
    __shared__ __align__(16) unsigned char sm[38912];
    const int b  = blockIdx.z, h = blockIdx.y;
    const int n0 = blockIdx.x * QT;
    const int t  = threadIdx.x;
    const int lane = t & 31, w = t >> 5;
    const int qg = w >> 1, kh = w & 1;
    const size_t bh = (size_t)b*NHEAD + h;
    const uint32_t smQ = smem_u32(sm);

    const uint8_t* kg0 = kT8 + bh*NPIX*HDIM;
    const __nv_bfloat16* vg0 = vT + (bh*NPIX)*HDIM;

    auto copy_kv = [&](int m0, int bb) {
        uint32_t kb = smQ + 6144 + bb*16384;
        uint32_t vbp = kb + 6144;
        const uint8_t* kg = kg0 + (size_t)m0*HDIM;
        const __nv_bfloat16* vg = vg0 + (size_t)m0*HDIM;
        CP_ASYNC16(kb + (t>>1)*RSQ + (t&1)*16,        kg + t*16);
        CP_ASYNC16(vbp + (t>>2)*RSV + (t&3)*16,       vg + (t>>2)*HDIM + (t&3)*8);
        CP_ASYNC16(vbp + ((t>>2)+64)*RSV + (t&3)*16,  vg + ((t>>2)+64)*HDIM + (t&3)*8);
        CP_COMMIT();
    };

    {
        const uint8_t* qg8 = qT8 + (bh*NPIX + (size_t)n0)*HDIM;
        CP_ASYNC16(smQ + (t>>1)*RSQ + (t&1)*16, qg8 + t*16);
        CP_COMMIT();
        copy_kv(0, 0);
        CP_WAIT0();
    }
    __syncthreads();

    uint32_t aq[2][4];
    #pragma unroll
    for (int mf = 0; mf < 2; mf++) {
        int r  = qg*32 + mf*16 + (lane & 7) + ((lane >> 3) & 1)*8;
        int cb = (lane >> 4)*16;
        ldsm_x4(smQ + r*RSQ + cb, aq[mf][0],aq[mf][1],aq[mf][2],aq[mf][3]);
    }

    float osum[2][4][4] = {};
    float ssum[2][4] = {};
    const int krow = (lane & 7) + (lane >> 4)*8;
    const int kcol = ((lane >> 3) & 1)*16;
    const int vrow = (lane & 7) + ((lane >> 3) & 1)*8;
    const int vcol = (lane >> 4)*16;
    const int kb0  = kh*64;

    int buf = 0;
    for (int kt = 0; kt < NKT; kt++) {
        if (kt + 1 < NKT) copy_kv((kt+1)*KT, buf ^ 1);
        const uint32_t smK = smQ + 6144 + buf*16384;
        const uint32_t smV = smK + 6144;

        #pragma unroll
        for (int jp = 0; jp < 4; jp++) {
            uint32_t kbase = smK + (kb0 + jp*16 + krow)*RSQ + kcol;
            uint32_t b0,b1,b2,b3;
            ldsm_x4(kbase, b0,b1,b2,b3);
            uint32_t vbase = smV + (kb0 + jp*16 + vrow)*RSV + vcol;
            uint32_t v0,v1,v2,v3,v4,v5,v6,v7;
            ldsm_x4_t(vbase,      v0,v1,v2,v3);
            ldsm_x4_t(vbase + 32, v4,v5,v6,v7);
            #pragma unroll
            for (int mf = 0; mf < 2; mf++) {
                float c0[4] = {0.f,0.f,0.f,0.f};
                float c1[4] = {0.f,0.f,0.f,0.f};
                mma_fp8(c0, aq[mf][0],aq[mf][1],aq[mf][2],aq[mf][3], b0,b1);
                mma_fp8(c1, aq[mf][0],aq[mf][1],aq[mf][2],aq[mf][3], b2,b3);
                uint32_t a0 = ex2_bf16x2(pack_bf16x2(c0[0], c0[1]));
                uint32_t a1 = ex2_bf16x2(pack_bf16x2(c0[2], c0[3]));
                uint32_t a2 = ex2_bf16x2(pack_bf16x2(c1[0], c1[1]));
                uint32_t a3 = ex2_bf16x2(pack_bf16x2(c1[2], c1[3]));
                mma_bf16(ssum[mf],    a0,a1,a2,a3, ONESB, ONESB);
                mma_bf16(osum[mf][0], a0,a1,a2,a3, v0,v1);
                mma_bf16(osum[mf][1], a0,a1,a2,a3, v2,v3);
                mma_bf16(osum[mf][2], a0,a1,a2,a3, v4,v5);
                mma_bf16(osum[mf][3], a0,a1,a2,a3, v6,v7);
            }
        }
        if (kt + 1 < NKT) CP_WAIT0();
        __syncthreads();
        buf ^= 1;
    }

    float* red = (float*)(sm + 16384);   // 4 qg x 40 vals x 32 lanes = 20 KB
    if (kh == 1) {
        #pragma unroll
        for (int mf = 0; mf < 2; mf++) {
            #pragma unroll
            for (int nj = 0; nj < 4; nj++)
                #pragma unroll
                for (int q = 0; q < 4; q++)
                    red[(qg*40 + mf*16 + nj*4 + q)*32 + lane] = osum[mf][nj][q];
            #pragma unroll
            for (int q = 0; q < 4; q++)
                red[(qg*40 + 32 + mf*4 + q)*32 + lane] = ssum[mf][q];
        }
    }
    __syncthreads();

    float* stage = (float*)sm;           // [32 d][128 q], 16 KB
    if (kh == 0) {
        #pragma unroll
        for (int mf = 0; mf < 2; mf++) {
            #pragma unroll
            for (int nj = 0; nj < 4; nj++)
                #pragma unroll
                for (int q = 0; q < 4; q++)
                    osum[mf][nj][q] += red[(qg*40 + mf*16 + nj*4 + q)*32 + lane];
            ssum[mf][0] += red[(qg*40 + 32 + mf*4 + 0)*32 + lane];
            ssum[mf][2] += red[(qg*40 + 32 + mf*4 + 2)*32 + lane];
        }
        #pragma unroll
        for (int mf = 0; mf < 2; mf++) {
            float inv0 = 1.f / ssum[mf][0], inv1 = 1.f / ssum[mf][2];
            int rl = qg*32 + mf*16 + (lane >> 2), rh = rl + 8;
            int d0 = (lane & 3)*2;
            #pragma unroll
            for (int nj = 0; nj < 4; nj++) {
                stage[(nj*8 + d0    )*128 + rl] = osum[mf][nj][0]*inv0;
                stage[(nj*8 + d0 + 1)*128 + rl] = osum[mf][nj][1]*inv0;
                stage[(nj*8 + d0    )*128 + rh] = osum[mf][nj][2]*inv1;
                stage[(nj*8 + d0 + 1)*128 + rh] = osum[mf][nj][3]*inv1;
            }
        }
    }
    __syncthreads();

    // o + pe -> bf16 (pairs along q)
    size_t obase = ((size_t)b*CCH + h*HDIM)*NPIX + n0;
    #pragma unroll
    for (int i = 0; i < 8; i++) {
        int idx = t + i*256;                 // 0..2047 pairs
        int d = idx >> 6, qp = (idx & 63) * 2;
        size_t g = obase + (size_t)d*NPIX + qp;
        float v0 = stage[d*128 + qp]     + pe[g];
        float v1 = stage[d*128 + qp + 1] + pe[g + 1];
        *(uint32_t*)&o_out[g] = pack_bf16x2(v0, v1);
    }
}

// ============================================================================
extern "C" void kernel_launch(void* const* d_in, const int* in_sizes, int n_in,
                              void* d_out, int out_size)
{
    const float* x      = (const float*)d_in[0];
    const float* qk_w   = (const float*)d_in[1];
    const float* qk_b   = (const float*)d_in[2];
    const float* v_w    = (const float*)d_in[3];
    const float* v_b    = (const float*)d_in[4];
    const float* pe_w   = (const float*)d_in[5];
    const float* pe_b   = (const float*)d_in[6];
    const float* proj_w = (const float*)d_in[7];
    const float* proj_b = (const float*)d_in[8];
    const float* fc1_w  = (const float*)d_in[9];
    const float* fc1_b  = (const float*)d_in[10];
    const float* fc2_w  = (const float*)d_in[11];
    const float* fc2_b  = (const float*)d_in[12];
    float* out = (float*)d_out;

    float *vb, *peb, *x1b;
    uint8_t *q8b, *k8b;
    __nv_bfloat16 *vbb, *obb, *x1bb, *hbb;
    cudaGetSymbolAddress((void**)&vb,   g_v);
    cudaGetSymbolAddress((void**)&peb,  g_pe);
    cudaGetSymbolAddress((void**)&x1b,  g_x1);
    cudaGetSymbolAddress((void**)&q8b,  g_q8);
    cudaGetSymbolAddress((void**)&k8b,  g_k8);
    cudaGetSymbolAddress((void**)&vbb,  g_vb);
    cudaGetSymbolAddress((void**)&obb,  g_ob);
    cudaGetSymbolAddress((void**)&x1bb, g_x1b);
    cudaGetSymbolAddress((void**)&hbb,  g_hb);

    const int NT = NPIX / 64;   // 36

    // qkv (tf32): by 0..7 -> q/k e4m3, by 8..11 -> v (fp32 + bf16)
    gemm_qkv_kernel<CCH><<<dim3(NT, 12, BATCH), 128>>>(
        x, qk_w, qk_b, v_w, v_b, vb, q8b, k8b);
    // pe = dwconv7x7(v)
    dwconv_kernel<<<dim3(CCH, BATCH), 256>>>(vb, pe_w, pe_b, peb);
    // o+pe -> bf16
    attn_mma_kernel<<<dim3(NPIX/QT, NHEAD, BATCH), 256>>>(q8b, k8b, vbb, peb, obb);
    // x1 = x + proj(o+pe): fp32 + bf16 copies
    gemm_bf16_kernel<CCH, 2, 1><<<dim3(NT, 4, BATCH), 128>>>(
        obb, proj_w, proj_b, x, x1b, x1bb, CCH);
    // h = silu(fc1(x1)): bf16 only
    gemm_bf16_kernel<CCH, 1, 2><<<dim3(NT, 8, BATCH), 128>>>(
        x1bb, fc1_w, fc1_b, nullptr, nullptr, hbb, HID);
    // out = x1 + fc2(h): fp32
    gemm_bf16_kernel<HID, 2, 0><<<dim3(NT, 4, BATCH), 128>>>(
        hbb, fc2_w, fc2_b, x1b, out, nullptr, CCH);
}

// round 15
// speedup vs baseline: 1.2987x; 1.1087x over previous
#include <cuda_runtime.h>
#include <cuda_bf16.h>
#include <math.h>
#include <cstdint>

#define BATCH 2
#define CCH   256
#define HSZ   48
#define NPIX  (HSZ*HSZ)     // 2304
#define NHEAD 8
#define HDIM  32
#define HID   512
#define QT    128
#define KT    128
#define NKT   (NPIX/KT)     // 18
#define RSQ   48            // fp8 q/k smem row stride
#define RSV   80            // bf16 v smem row stride
#define RSA   80            // bf16 gemm A row stride (64B data + 16 pad)
#define RSB   144           // bf16 gemm B row stride (128B data + 16 pad)
#define ONESB 0x3F803F80u   // bf16x2 (1.0, 1.0)

// ---- device scratch ----
__device__ float g_v [BATCH*CCH*NPIX];
__device__ float g_pe[BATCH*CCH*NPIX];
__device__ float g_x1[BATCH*CCH*NPIX];
__device__ uint8_t g_q8[BATCH*NHEAD*NPIX*HDIM];        // e4m3 [b,h][n][d], q pre-scaled
__device__ uint8_t g_k8[BATCH*NHEAD*NPIX*HDIM];        // e4m3
__device__ __nv_bfloat16 g_vb [BATCH*NHEAD*NPIX*HDIM]; // bf16 [b,h][n][d]
__device__ __nv_bfloat16 g_ob [BATCH*CCH*NPIX];        // bf16 o+pe
__device__ __nv_bfloat16 g_x1b[BATCH*CCH*NPIX];        // bf16 x1
__device__ __nv_bfloat16 g_hb [BATCH*HID*NPIX];        // bf16 h
__device__ __nv_bfloat16 g_xb [BATCH*CCH*NPIX];        // bf16 x
__device__ __nv_bfloat16 g_wqk [2*CCH*CCH];            // bf16 weights
__device__ __nv_bfloat16 g_wv  [CCH*CCH];
__device__ __nv_bfloat16 g_wproj[CCH*CCH];
__device__ __nv_bfloat16 g_wfc1[HID*CCH];
__device__ __nv_bfloat16 g_wfc2[CCH*HID];

__device__ __forceinline__ uint32_t smem_u32(const void* p) {
    uint32_t a;
    asm("{ .reg .u64 t; cvta.to.shared.u64 t, %1; cvt.u32.u64 %0, t; }" : "=r"(a) : "l"(p));
    return a;
}
#define CP_ASYNC16(dst, src) \
    asm volatile("cp.async.ca.shared.global [%0], [%1], 16;" :: "r"(dst), "l"(src))
#define CP_COMMIT() asm volatile("cp.async.commit_group;" ::: "memory")
#define CP_WAIT0()  asm volatile("cp.async.wait_group 0;" ::: "memory")

__device__ __forceinline__ void ldsm_x4(uint32_t addr, uint32_t &r0, uint32_t &r1, uint32_t &r2, uint32_t &r3) {
    asm volatile("ldmatrix.sync.aligned.m8n8.x4.shared.b16 {%0,%1,%2,%3}, [%4];"
        : "=r"(r0),"=r"(r1),"=r"(r2),"=r"(r3) : "r"(addr));
}
__device__ __forceinline__ void ldsm_x4_t(uint32_t addr, uint32_t &r0, uint32_t &r1, uint32_t &r2, uint32_t &r3) {
    asm volatile("ldmatrix.sync.aligned.m8n8.x4.trans.shared.b16 {%0,%1,%2,%3}, [%4];"
        : "=r"(r0),"=r"(r1),"=r"(r2),"=r"(r3) : "r"(addr));
}
__device__ __forceinline__ void mma_bf16(float* c,
    uint32_t a0,uint32_t a1,uint32_t a2,uint32_t a3,uint32_t b0,uint32_t b1) {
    asm volatile("mma.sync.aligned.m16n8k16.row.col.f32.bf16.bf16.f32 "
        "{%0,%1,%2,%3}, {%4,%5,%6,%7}, {%8,%9}, {%0,%1,%2,%3};"
        : "+f"(c[0]),"+f"(c[1]),"+f"(c[2]),"+f"(c[3])
        : "r"(a0),"r"(a1),"r"(a2),"r"(a3),"r"(b0),"r"(b1));
}
__device__ __forceinline__ void mma_fp8(float* c,
    uint32_t a0,uint32_t a1,uint32_t a2,uint32_t a3,uint32_t b0,uint32_t b1) {
    asm volatile("mma.sync.aligned.m16n8k32.row.col.f32.e4m3.e4m3.f32 "
        "{%0,%1,%2,%3}, {%4,%5,%6,%7}, {%8,%9}, {%0,%1,%2,%3};"
        : "+f"(c[0]),"+f"(c[1]),"+f"(c[2]),"+f"(c[3])
        : "r"(a0),"r"(a1),"r"(a2),"r"(a3),"r"(b0),"r"(b1));
}
__device__ __forceinline__ uint32_t pack_bf16x2(float lo, float hi) {
    uint32_t r; asm("cvt.rn.bf16x2.f32 %0, %1, %2;" : "=r"(r) : "f"(hi), "f"(lo)); return r;
}
__device__ __forceinline__ uint32_t ex2_bf16x2(uint32_t x) {
    uint32_t r; asm("ex2.approx.ftz.bf16x2 %0, %1;" : "=r"(r) : "r"(x)); return r;
}
__device__ __forceinline__ uint32_t pack_e4m3_4(float f0, float f1, float f2, float f3) {
    unsigned short lo, hi;
    asm("cvt.rn.satfinite.e4m3x2.f32 %0, %1, %2;" : "=h"(lo) : "f"(f1), "f"(f0));
    asm("cvt.rn.satfinite.e4m3x2.f32 %0, %1, %2;" : "=h"(hi) : "f"(f3), "f"(f2));
    return (uint32_t)lo | ((uint32_t)hi << 16);
}

// ============================================================================
// Prep: fp32 -> bf16 for x and all weights. One float4 per thread.
// Layout: [0,294912) x | then qk_w 32768 | v_w 16384 | proj_w 16384 |
// fc1_w 32768 | fc2_w 32768 float4 groups.
// ============================================================================
__global__ void __launch_bounds__(256) prep_bf16_kernel(
    const float* __restrict__ x,     const float* __restrict__ qk_w,
    const float* __restrict__ v_w,   const float* __restrict__ proj_w,
    const float* __restrict__ fc1_w, const float* __restrict__ fc2_w)
{
    int idx = blockIdx.x * 256 + threadIdx.x;
    const float* src; __nv_bfloat16* dst; int off;
    if (idx < 294912)      { src = x;      dst = g_xb;   off = idx; }
    else {
        int j = idx - 294912;
        if (j < 32768)      { src = qk_w;   dst = g_wqk;  off = j; }
        else if (j < 49152) { src = v_w;    dst = g_wv;   off = j - 32768; }
        else if (j < 65536) { src = proj_w; dst = g_wproj; off = j - 49152; }
        else if (j < 98304) { src = fc1_w;  dst = g_wfc1; off = j - 65536; }
        else                { src = fc2_w;  dst = g_wfc2; off = j - 98304; }
    }
    float4 v4 = *(const float4*)&src[(size_t)off*4];
    uint32_t lo = pack_bf16x2(v4.x, v4.y);
    uint32_t hi = pack_bf16x2(v4.z, v4.w);
    *(uint2*)&dst[(size_t)off*4] = make_uint2(lo, hi);
}

// ============================================================================
// Unified bf16 GEMM: 64o x 64n, 128 thr (2x2 warps of 32x32), 2-stage
// cp.async for BOTH bf16 operands. EPI: 0 none, 1 silu, 2 residual.
// MODE: 0 fp32 out, 1 fp32+bf16 aux, 2 bf16 aux only, 3 qkv fused.
// Buf: A[64*RSA]=5120B + B[32*RSB]=4608B = 9728B x2; stage fp32 [64][68].
// ============================================================================
template<int KDIM, int EPI, int MODE>
__global__ void __launch_bounds__(128) gemm_bf16_kernel(
    const __nv_bfloat16* __restrict__ in, const __nv_bfloat16* __restrict__ wA,
    const float* __restrict__ bias, const __nv_bfloat16* __restrict__ wA2,
    const float* __restrict__ bias2, const float* __restrict__ res,
    float* __restrict__ out, __nv_bfloat16* __restrict__ aux, int Odim,
    uint8_t* __restrict__ bq, uint8_t* __restrict__ bk)
{
    __shared__ __align__(16) unsigned char sm[2*9728];
    float* stage = (float*)sm;               // [64][68] fp32 overlay

    const int b  = blockIdx.z;
    const int by = blockIdx.y;
    const int n0 = blockIdx.x * 64;
    const int t  = threadIdx.x;
    const int lane = t & 31, wrp = t >> 5;
    const int wy = wrp >> 1, wx = wrp & 1;

    const __nv_bfloat16* W = wA;  const float* Bias = bias;
    int o0 = by * 64;
    bool vpath = false;
    if (MODE == 3 && by >= 8) { W = wA2; Bias = bias2; o0 = (by - 8) * 64; vpath = true; }

    float c[2][4][4];
    #pragma unroll
    for (int mi=0;mi<2;mi++) for (int nj=0;nj<4;nj++) for (int q=0;q<4;q++) c[mi][nj][q]=0.f;

    const uint32_t smBase = smem_u32(sm);

    // one k-block: A 64 rows x 32 k bf16 (4 chunks/row), B 32 rows x 64 n (8 chunks/row)
    auto copy_tile = [&](int k0, int bb) {
        uint32_t Ab = smBase + bb*9728;
        uint32_t Bb = Ab + 5120;
        #pragma unroll
        for (int i = 0; i < 2; i++) {
            int ci = t + i*128;                      // 0..255
            int o = ci >> 2, kq = ci & 3;
            CP_ASYNC16(Ab + (uint32_t)(o*RSA + kq*16),
                       &W[(size_t)(o0 + o)*KDIM + k0 + kq*8]);
        }
        #pragma unroll
        for (int i = 0; i < 2; i++) {
            int ci = t + i*128;                      // 0..255
            int kr = ci >> 3, nc = ci & 7;
            CP_ASYNC16(Bb + (uint32_t)(kr*RSB + nc*16),
                       &in[((size_t)b*KDIM + k0 + kr)*NPIX + n0 + nc*8]);
        }
        CP_COMMIT();
    };

    copy_tile(0, 0);
    CP_WAIT0();
    __syncthreads();

    const int KB = KDIM / 32;
    int buf = 0;
    for (int kb = 0; kb < KB; kb++) {
        if (kb + 1 < KB) copy_tile((kb+1)*32, buf ^ 1);
        const uint32_t Ab = smBase + buf*9728;
        const uint32_t Bb = Ab + 5120;
        #pragma unroll
        for (int kk = 0; kk < 2; kk++) {
            uint32_t a[2][4];
            #pragma unroll
            for (int mi = 0; mi < 2; mi++) {
                int row = wy*32 + mi*16 + (lane & 7) + ((lane >> 3) & 1)*8;
                ldsm_x4(Ab + (uint32_t)(row*RSA + kk*32 + (lane>>4)*16),
                        a[mi][0], a[mi][1], a[mi][2], a[mi][3]);
            }
            int brow = kk*16 + (lane & 7) + ((lane >> 3) & 1)*8;
            uint32_t bbase = Bb + (uint32_t)(brow*RSB + wx*64 + (lane>>4)*16);
            uint32_t v0,v1,v2,v3,v4,v5,v6,v7;
            ldsm_x4_t(bbase,      v0,v1,v2,v3);
            ldsm_x4_t(bbase + 32, v4,v5,v6,v7);
            #pragma unroll
            for (int mi = 0; mi < 2; mi++) {
                mma_bf16(c[mi][0], a[mi][0],a[mi][1],a[mi][2],a[mi][3], v0,v1);
                mma_bf16(c[mi][1], a[mi][0],a[mi][1],a[mi][2],a[mi][3], v2,v3);
                mma_bf16(c[mi][2], a[mi][0],a[mi][1],a[mi][2],a[mi][3], v4,v5);
                mma_bf16(c[mi][3], a[mi][0],a[mi][1],a[mi][2],a[mi][3], v6,v7);
            }
        }
        if (kb + 1 < KB) CP_WAIT0();
        __syncthreads();
        buf ^= 1;
    }

    // ---- stage accums (+bias) into smem [64][68] fp32 ----
    #pragma unroll
    for (int mi = 0; mi < 2; mi++) {
        int ol = wy*32 + mi*16 + (lane >> 2);
        float bv0 = Bias[o0 + ol];
        float bv1 = Bias[o0 + ol + 8];
        #pragma unroll
        for (int nj = 0; nj < 4; nj++) {
            int nl = wx*32 + nj*8 + (lane & 3)*2;
            *(float2*)&stage[ol*68 + nl]     = make_float2(c[mi][nj][0]+bv0, c[mi][nj][1]+bv0);
            *(float2*)&stage[(ol+8)*68 + nl] = make_float2(c[mi][nj][2]+bv1, c[mi][nj][3]+bv1);
        }
    }
    __syncthreads();

    if (MODE != 3) {
        #pragma unroll
        for (int i = 0; i < 8; i++) {
            int idx = t + i*128;                 // 0..1023
            int o = idx >> 4, np = (idx & 15) * 4;
            size_t g = ((size_t)b*Odim + o0 + o)*NPIX + n0 + np;
            float v[4];
            v[0] = stage[o*68 + np];     v[1] = stage[o*68 + np + 1];
            v[2] = stage[o*68 + np + 2]; v[3] = stage[o*68 + np + 3];
            if (EPI == 1) {
                #pragma unroll
                for (int j = 0; j < 4; j++) v[j] = v[j] / (1.f + __expf(-v[j]));
            } else if (EPI == 2) {
                float4 r4 = *(const float4*)&res[g];
                v[0] += r4.x; v[1] += r4.y; v[2] += r4.z; v[3] += r4.w;
            }
            if (MODE != 2)
                *(float4*)&out[g] = make_float4(v[0], v[1], v[2], v[3]);
            if (MODE != 0) {
                uint32_t lo = pack_bf16x2(v[0], v[1]);
                uint32_t hi = pack_bf16x2(v[2], v[3]);
                *(uint2*)&aux[g] = make_uint2(lo, hi);
            }
        }
    } else {
        if (!vpath) {
            const float SCQ = (float)(0.17677669529663687 * 1.4426950408889634);
            size_t bh = (size_t)b*NHEAD + by;
            #pragma unroll
            for (int i = 0; i < 4; i++) {
                int idx = t + i*128;            // < 512
                int isk = idx >> 8;
                int r = idx & 255;
                int n = r >> 2, dq = (r & 3) * 8;
                float sc = isk ? 1.f : SCQ;
                float f[8];
                #pragma unroll
                for (int j = 0; j < 8; j++)
                    f[j] = stage[(isk*32 + dq + j)*68 + n] * sc;
                uint32_t lo = pack_e4m3_4(f[0],f[1],f[2],f[3]);
                uint32_t hi = pack_e4m3_4(f[4],f[5],f[6],f[7]);
                uint8_t* dst = isk ? bk : bq;
                *(uint2*)&dst[((bh*NPIX + n0 + n))*HDIM + dq] = make_uint2(lo, hi);
            }
        } else {
            #pragma unroll
            for (int i = 0; i < 8; i++) {
                int idx = t + i*128;
                int o = idx >> 4, nq = (idx & 15) * 4;
                float4 v4 = *(float4*)&stage[o*68 + nq];
                *(float4*)&out[((size_t)b*CCH + o0 + o)*NPIX + n0 + nq] = v4;
            }
            #pragma unroll
            for (int i = 0; i < 4; i++) {
                int idx = t + i*128;            // < 512
                int n = idx >> 3, row = (idx & 7) * 8;
                int ch = o0 + row;
                size_t bh = (size_t)b*NHEAD + (ch >> 5);
                int d = ch & 31;
                __nv_bfloat16 p8[8];
                #pragma unroll
                for (int j = 0; j < 8; j++)
                    p8[j] = __float2bfloat16(stage[(row + j)*68 + n]);
                *(uint4*)&g_vb[(bh*NPIX + n0 + n)*HDIM + d] = *(uint4*)p8;
            }
        }
    }
}

// ============================================================================
// Depthwise 7x7 conv
// ============================================================================
__global__ void __launch_bounds__(256) dwconv_kernel(
    const float* __restrict__ vin, const float* __restrict__ pw,
    const float* __restrict__ pb, float* __restrict__ out)
{
    __shared__ float plane[54*54];
    __shared__ float wc[49];
    const int c = blockIdx.x, b = blockIdx.y;
    const int t = threadIdx.x;
    const float* src = &vin[((size_t)b*CCH + c)*NPIX];

    if (t < 49) wc[t] = pw[c*49 + t];
    for (int idx = t; idx < 54*54; idx += 256) {
        int gy = idx / 54 - 3, gx = idx % 54 - 3;
        plane[idx] = (gy >= 0 && gy < HSZ && gx >= 0 && gx < HSZ) ? src[gy*HSZ + gx] : 0.f;
    }
    __syncthreads();
    float bias = pb[c];
    for (int p = t; p < NPIX; p += 256) {
        int y = p / HSZ, x = p % HSZ;
        float acc = bias;
        #pragma unroll
        for (int dy = 0; dy < 7; dy++)
            #pragma unroll
            for (int dx = 0; dx < 7; dx++)
                acc += plane[(y+dy)*54 + (x+dx)] * wc[dy*7 + dx];
        out[((size_t)b*CCH + c)*NPIX + p] = acc;
    }
}

// ============================================================================
// Flash attention: fp8 e4m3 Q*K^T + bf16 P*V. Split-K over warps.
// Epilogue: o_norm + pe -> bf16 g_ob.
// ============================================================================
__global__ void __launch_bounds__(256, 2) attn_mma_kernel(
    const uint8_t* __restrict__ qT8, const uint8_t* __restrict__ kT8,
    const __nv_bfloat16* __restrict__ vT, const float* __restrict__ pe,
    __nv_bfloat16* __restrict__ o_out)
{
    __shared__ __align__(16) unsigned char sm[38912];
    const int b  = blockIdx.z, h = blockIdx.y;
    const int n0 = blockIdx.x * QT;
    const int t  = threadIdx.x;
    const int lane = t & 31, w = t >> 5;
    const int qg = w >> 1, kh = w & 1;
    const size_t bh = (size_t)b*NHEAD + h;
    const uint32_t smQ = smem_u32(sm);

    const uint8_t* kg0 = kT8 + bh*NPIX*HDIM;
    const __nv_bfloat16* vg0 = vT + (bh*NPIX)*HDIM;

    auto copy_kv = [&](int m0, int bb) {
        uint32_t kb = smQ + 6144 + bb*16384;
        uint32_t vbp = kb + 6144;
        const uint8_t* kg = kg0 + (size_t)m0*HDIM;
        const __nv_bfloat16* vg = vg0 + (size_t)m0*HDIM;
        CP_ASYNC16(kb + (t>>1)*RSQ + (t&1)*16,        kg + t*16);
        CP_ASYNC16(vbp + (t>>2)*RSV + (t&3)*16,       vg + (t>>2)*HDIM + (t&3)*8);
        CP_ASYNC16(vbp + ((t>>2)+64)*RSV + (t&3)*16,  vg + ((t>>2)+64)*HDIM + (t&3)*8);
        CP_COMMIT();
    };

    {
        const uint8_t* qg8 = qT8 + (bh*NPIX + (size_t)n0)*HDIM;
        CP_ASYNC16(smQ + (t>>1)*RSQ + (t&1)*16, qg8 + t*16);
        CP_COMMIT();
        copy_kv(0, 0);
        CP_WAIT0();
    }
    __syncthreads();

    uint32_t aq[2][4];
    #pragma unroll
    for (int mf = 0; mf < 2; mf++) {
        int r  = qg*32 + mf*16 + (lane & 7) + ((lane >> 3) & 1)*8;
        int cb = (lane >> 4)*16;
        ldsm_x4(smQ + r*RSQ + cb, aq[mf][0],aq[mf][1],aq[mf][2],aq[mf][3]);
    }

    float osum[2][4][4] = {};
    float ssum[2][4] = {};
    const int krow = (lane & 7) + (lane >> 4)*8;
    const int kcol = ((lane >> 3) & 1)*16;
    const int vrow = (lane & 7) + ((lane >> 3) & 1)*8;
    const int vcol = (lane >> 4)*16;
    const int kb0  = kh*64;

    int buf = 0;
    for (int kt = 0; kt < NKT; kt++) {
        if (kt + 1 < NKT) copy_kv((kt+1)*KT, buf ^ 1);
        const uint32_t smK = smQ + 6144 + buf*16384;
        const uint32_t smV = smK + 6144;

        #pragma unroll
        for (int jp = 0; jp < 4; jp++) {
            uint32_t kbase = smK + (kb0 + jp*16 + krow)*RSQ + kcol;
            uint32_t b0,b1,b2,b3;
            ldsm_x4(kbase, b0,b1,b2,b3);
            uint32_t vbase = smV + (kb0 + jp*16 + vrow)*RSV + vcol;
            uint32_t v0,v1,v2,v3,v4,v5,v6,v7;
            ldsm_x4_t(vbase,      v0,v1,v2,v3);
            ldsm_x4_t(vbase + 32, v4,v5,v6,v7);
            #pragma unroll
            for (int mf = 0; mf < 2; mf++) {
                float c0[4] = {0.f,0.f,0.f,0.f};
                float c1[4] = {0.f,0.f,0.f,0.f};
                mma_fp8(c0, aq[mf][0],aq[mf][1],aq[mf][2],aq[mf][3], b0,b1);
                mma_fp8(c1, aq[mf][0],aq[mf][1],aq[mf][2],aq[mf][3], b2,b3);
                uint32_t a0 = ex2_bf16x2(pack_bf16x2(c0[0], c0[1]));
                uint32_t a1 = ex2_bf16x2(pack_bf16x2(c0[2], c0[3]));
                uint32_t a2 = ex2_bf16x2(pack_bf16x2(c1[0], c1[1]));
                uint32_t a3 = ex2_bf16x2(pack_bf16x2(c1[2], c1[3]));
                mma_bf16(ssum[mf],    a0,a1,a2,a3, ONESB, ONESB);
                mma_bf16(osum[mf][0], a0,a1,a2,a3, v0,v1);
                mma_bf16(osum[mf][1], a0,a1,a2,a3, v2,v3);
                mma_bf16(osum[mf][2], a0,a1,a2,a3, v4,v5);
                mma_bf16(osum[mf][3], a0,a1,a2,a3, v6,v7);
            }
        }
        if (kt + 1 < NKT) CP_WAIT0();
        __syncthreads();
        buf ^= 1;
    }

    float* red = (float*)(sm + 16384);   // 4 qg x 40 vals x 32 lanes = 20 KB
    if (kh == 1) {
        #pragma unroll
        for (int mf = 0; mf < 2; mf++) {
            #pragma unroll
            for (int nj = 0; nj < 4; nj++)
                #pragma unroll
                for (int q = 0; q < 4; q++)
                    red[(qg*40 + mf*16 + nj*4 + q)*32 + lane] = osum[mf][nj][q];
            #pragma unroll
            for (int q = 0; q < 4; q++)
                red[(qg*40 + 32 + mf*4 + q)*32 + lane] = ssum[mf][q];
        }
    }
    __syncthreads();

    float* stage = (float*)sm;           // [32 d][128 q], 16 KB
    if (kh == 0) {
        #pragma unroll
        for (int mf = 0; mf < 2; mf++) {
            #pragma unroll
            for (int nj = 0; nj < 4; nj++)
                #pragma unroll
                for (int q = 0; q < 4; q++)
                    osum[mf][nj][q] += red[(qg*40 + mf*16 + nj*4 + q)*32 + lane];
            ssum[mf][0] += red[(qg*40 + 32 + mf*4 + 0)*32 + lane];
            ssum[mf][2] += red[(qg*40 + 32 + mf*4 + 2)*32 + lane];
        }
        #pragma unroll
        for (int mf = 0; mf < 2; mf++) {
            float inv0 = 1.f / ssum[mf][0], inv1 = 1.f / ssum[mf][2];
            int rl = qg*32 + mf*16 + (lane >> 2), rh = rl + 8;
            int d0 = (lane & 3)*2;
            #pragma unroll
            for (int nj = 0; nj < 4; nj++) {
                stage[(nj*8 + d0    )*128 + rl] = osum[mf][nj][0]*inv0;
                stage[(nj*8 + d0 + 1)*128 + rl] = osum[mf][nj][1]*inv0;
                stage[(nj*8 + d0    )*128 + rh] = osum[mf][nj][2]*inv1;
                stage[(nj*8 + d0 + 1)*128 + rh] = osum[mf][nj][3]*inv1;
            }
        }
    }
    __syncthreads();

    size_t obase = ((size_t)b*CCH + h*HDIM)*NPIX + n0;
    #pragma unroll
    for (int i = 0; i < 8; i++) {
        int idx = t + i*256;                 // 0..2047 pairs
        int d = idx >> 6, qp = (idx & 63) * 2;
        size_t g = obase + (size_t)d*NPIX + qp;
        float v0 = stage[d*128 + qp]     + pe[g];
        float v1 = stage[d*128 + qp + 1] + pe[g + 1];
        *(uint32_t*)&o_out[g] = pack_bf16x2(v0, v1);
    }
}

// ============================================================================
extern "C" void kernel_launch(void* const* d_in, const int* in_sizes, int n_in,
                              void* d_out, int out_size)
{
    const float* x      = (const float*)d_in[0];
    const float* qk_w   = (const float*)d_in[1];
    const float* qk_b   = (const float*)d_in[2];
    const float* v_w    = (const float*)d_in[3];
    const float* v_b    = (const float*)d_in[4];
    const float* pe_w   = (const float*)d_in[5];
    const float* pe_b   = (const float*)d_in[6];
    const float* proj_w = (const float*)d_in[7];
    const float* proj_b = (const float*)d_in[8];
    const float* fc1_w  = (const float*)d_in[9];
    const float* fc1_b  = (const float*)d_in[10];
    const float* fc2_w  = (const float*)d_in[11];
    const float* fc2_b  = (const float*)d_in[12];
    float* out = (float*)d_out;

    float *vb, *peb, *x1b;
    uint8_t *q8b, *k8b;
    __nv_bfloat16 *vbb, *obb, *x1bb, *hbb, *xbb, *wqk, *wv, *wproj, *wfc1, *wfc2;
    cudaGetSymbolAddress((void**)&vb,    g_v);
    cudaGetSymbolAddress((void**)&peb,   g_pe);
    cudaGetSymbolAddress((void**)&x1b,   g_x1);
    cudaGetSymbolAddress((void**)&q8b,   g_q8);
    cudaGetSymbolAddress((void**)&k8b,   g_k8);
    cudaGetSymbolAddress((void**)&vbb,   g_vb);
    cudaGetSymbolAddress((void**)&obb,   g_ob);
    cudaGetSymbolAddress((void**)&x1bb,  g_x1b);
    cudaGetSymbolAddress((void**)&hbb,   g_hb);
    cudaGetSymbolAddress((void**)&xbb,   g_xb);
    cudaGetSymbolAddress((void**)&wqk,   g_wqk);
    cudaGetSymbolAddress((void**)&wv,    g_wv);
    cudaGetSymbolAddress((void**)&wproj, g_wproj);
    cudaGetSymbolAddress((void**)&wfc1,  g_wfc1);
    cudaGetSymbolAddress((void**)&wfc2,  g_wfc2);

    const int NT = NPIX / 64;   // 36

    // 0) bf16 conversions: x + all weights (425984 float4 / 256 = 1664 blocks)
    prep_bf16_kernel<<<1664, 256>>>(x, qk_w, v_w, proj_w, fc1_w, fc2_w);
    // 1) qkv (bf16): by 0..7 -> q/k e4m3, by 8..11 -> v (fp32 + bf16)
    gemm_bf16_kernel<CCH, 0, 3><<<dim3(NT, 12, BATCH), 128>>>(
        xbb, wqk, qk_b, wv, v_b, nullptr, vb, nullptr, CCH, q8b, k8b);
    // 2) pe = dwconv7x7(v)
    dwconv_kernel<<<dim3(CCH, BATCH), 256>>>(vb, pe_w, pe_b, peb);
    // 3) o+pe -> bf16
    attn_mma_kernel<<<dim3(NPIX/QT, NHEAD, BATCH), 256>>>(q8b, k8b, vbb, peb, obb);
    // 4) x1 = x + proj(o+pe): fp32 + bf16
    gemm_bf16_kernel<CCH, 2, 1><<<dim3(NT, 4, BATCH), 128>>>(
        obb, wproj, proj_b, nullptr, nullptr, x, x1b, x1bb, CCH, nullptr, nullptr);
    // 5) h = silu(fc1(x1)): bf16 only
    gemm_bf16_kernel<CCH, 1, 2><<<dim3(NT, 8, BATCH), 128>>>(
        x1bb, wfc1, fc1_b, nullptr, nullptr, nullptr, nullptr, hbb, HID, nullptr, nullptr);
    // 6) out = x1 + fc2(h): fp32
    gemm_bf16_kernel<HID, 2, 0><<<dim3(NT, 4, BATCH), 128>>>(
        hbb, wfc2, fc2_b, nullptr, nullptr, x1b, out, nullptr, CCH, nullptr, nullptr);
}